// round 2
// baseline (speedup 1.0000x reference)
#include <cuda_runtime.h>
#include <cstdint>

// ---------------------------------------------------------------------------
// Problem constants
// ---------------------------------------------------------------------------
#define NBOX   512
#define CCH    512
#define HH     50
#define WW     50
#define OUTB   7
#define FLATF  25088            // 512*7*7
#define CONVK  8192             // 512*4*4
#define M16    8192             // 512 * 16 conv output positions
#define FVS    4096

// ---------------------------------------------------------------------------
// Device scratch (allocation-free contract: __device__ globals)
// ---------------------------------------------------------------------------
__device__ __align__(16) float g_fmt[HH * WW * CCH];                 // [h*50+w][c]
__device__ __align__(16) float g_rois2[2 * NBOX * FLATF];            // rows 0..511 clean, 512..1023 noisy
__device__ __align__(16) float g_im2col[(size_t)M16 * CONVK];        // 268 MB
__device__ __align__(16) float g_convt[M16 * 512];                   // [n][pos][oc]
__device__ __align__(16) float g_xb[NBOX * CONVK];                   // [n][oc*16+pos]
__device__ __align__(16) float g_h1[M16 * 512];
__device__ float g_ns[NBOX];
__device__ __align__(16) float g_y6[2 * NBOX * FVS];
__device__ __align__(16) float g_y7[2 * NBOX * FVS];
__device__ float g_cls[2 * NBOX * 21];
__device__ float g_reg[2 * NBOX * 80];

// ---------------------------------------------------------------------------
// TF32 helpers
// ---------------------------------------------------------------------------
__device__ __forceinline__ float to_tf32(float x) {
    uint32_t u;
    asm("cvt.rna.tf32.f32 %0, %1;" : "=r"(u) : "f"(x));
    return __uint_as_float(u);
}

__device__ __forceinline__ void ldsm4(uint32_t r[4], const float* p) {
    uint32_t a = (uint32_t)__cvta_generic_to_shared(p);
    asm volatile("ldmatrix.sync.aligned.m8n8.x4.shared.b16 {%0,%1,%2,%3}, [%4];"
                 : "=r"(r[0]), "=r"(r[1]), "=r"(r[2]), "=r"(r[3]) : "r"(a));
}

__device__ __forceinline__ void mma_tf32(float d[4], const uint32_t a[4],
                                         uint32_t b0, uint32_t b1) {
    asm volatile("mma.sync.aligned.m16n8k8.row.col.f32.tf32.tf32.f32 "
                 "{%0,%1,%2,%3}, {%4,%5,%6,%7}, {%8,%9}, {%0,%1,%2,%3};"
                 : "+f"(d[0]), "+f"(d[1]), "+f"(d[2]), "+f"(d[3])
                 : "r"(a[0]), "r"(a[1]), "r"(a[2]), "r"(a[3]), "r"(b0), "r"(b1));
}

// ---------------------------------------------------------------------------
// Generic TF32 GEMM:  C[m][n] = act( sum_k A[m*K+k]*B[n*K+k] + bias[n] )
// BM=BN=128, BK=16, 256 threads (8 warps as 2x4), warp tile 64x32,
// mma m16n8k8 tf32, double-buffered SMEM, ldmatrix fragment loads.
// Requires K % 16 == 0 (true for 25088/8192/4096/512). M,N boundary-guarded.
// ---------------------------------------------------------------------------
template <bool RELU>
__global__ void __launch_bounds__(256)
gemm_tf32(const float* __restrict__ A, const float* __restrict__ Bw,
          const float* __restrict__ bias, float* __restrict__ C,
          int M, int N, int K)
{
    __shared__ __align__(16) float As[2][128][20];
    __shared__ __align__(16) float Bs[2][128][20];

    const int t    = threadIdx.x;
    const int lane = t & 31;
    const int wid  = t >> 5;
    const int m0   = blockIdx.y << 7;
    const int n0   = blockIdx.x << 7;
    const int wm0  = (wid >> 2) << 6;     // 0 or 64
    const int wn0  = (wid & 3) << 5;      // 0,32,64,96

    const int lrow = t >> 2;              // 0..63
    const int lcv  = (t & 3) << 2;        // 0,4,8,12

    // ldmatrix per-lane offsets (x4: lanes 0-7 m0, 8-15 m1, 16-23 m2, 24-31 m3)
    const int roff = (lane & 7) + ((lane & 8) ? 8 : 0);
    const int coff = (lane & 16) ? 4 : 0;

    float acc[4][4][4];
#pragma unroll
    for (int i = 0; i < 4; i++)
#pragma unroll
        for (int j = 0; j < 4; j++)
#pragma unroll
            for (int r = 0; r < 4; r++) acc[i][j][r] = 0.f;

    const int KT = K >> 4;

    float4 ra0, ra1, rb0, rb1;

#define GLOAD(KT_IDX)                                                           \
    {                                                                           \
        const int kk = ((KT_IDX) << 4) + lcv;                                   \
        const int r0 = m0 + lrow, r1 = m0 + 64 + lrow;                          \
        ra0 = (r0 < M) ? *(const float4*)(A + (size_t)r0 * K + kk)              \
                       : make_float4(0.f, 0.f, 0.f, 0.f);                       \
        ra1 = (r1 < M) ? *(const float4*)(A + (size_t)r1 * K + kk)              \
                       : make_float4(0.f, 0.f, 0.f, 0.f);                       \
        const int s0 = n0 + lrow, s1 = n0 + 64 + lrow;                          \
        rb0 = (s0 < N) ? *(const float4*)(Bw + (size_t)s0 * K + kk)             \
                       : make_float4(0.f, 0.f, 0.f, 0.f);                       \
        rb1 = (s1 < N) ? *(const float4*)(Bw + (size_t)s1 * K + kk)             \
                       : make_float4(0.f, 0.f, 0.f, 0.f);                       \
    }

#define SSTORE(BUF)                                                             \
    {                                                                           \
        float* p;                                                               \
        p = &As[BUF][lrow][lcv];                                                \
        p[0] = to_tf32(ra0.x); p[1] = to_tf32(ra0.y);                           \
        p[2] = to_tf32(ra0.z); p[3] = to_tf32(ra0.w);                           \
        p = &As[BUF][64 + lrow][lcv];                                           \
        p[0] = to_tf32(ra1.x); p[1] = to_tf32(ra1.y);                           \
        p[2] = to_tf32(ra1.z); p[3] = to_tf32(ra1.w);                           \
        p = &Bs[BUF][lrow][lcv];                                                \
        p[0] = to_tf32(rb0.x); p[1] = to_tf32(rb0.y);                           \
        p[2] = to_tf32(rb0.z); p[3] = to_tf32(rb0.w);                           \
        p = &Bs[BUF][64 + lrow][lcv];                                           \
        p[0] = to_tf32(rb1.x); p[1] = to_tf32(rb1.y);                           \
        p[2] = to_tf32(rb1.z); p[3] = to_tf32(rb1.w);                           \
    }

    GLOAD(0);
    SSTORE(0);
    __syncthreads();

    for (int kt = 0; kt < KT; kt++) {
        const int cur = kt & 1;
        const bool more = (kt + 1 < KT);
        if (more) GLOAD(kt + 1);

#pragma unroll
        for (int ks = 0; ks < 2; ks++) {
            uint32_t afr[4][4];
#pragma unroll
            for (int mi = 0; mi < 4; mi++)
                ldsm4(afr[mi], &As[cur][wm0 + mi * 16 + roff][ks * 8 + coff]);
            uint32_t bfr[2][4];
#pragma unroll
            for (int bj = 0; bj < 2; bj++)
                ldsm4(bfr[bj], &Bs[cur][wn0 + bj * 16 + roff][ks * 8 + coff]);
#pragma unroll
            for (int mi = 0; mi < 4; mi++)
#pragma unroll
                for (int nj = 0; nj < 4; nj++)
                    mma_tf32(acc[mi][nj], afr[mi],
                             bfr[nj >> 1][nj & 1], bfr[nj >> 1][2 + (nj & 1)]);
        }

        if (more) SSTORE(1 - cur);
        __syncthreads();
    }

    // Epilogue: bias + activation, boundary guarded
#pragma unroll
    for (int mi = 0; mi < 4; mi++) {
        const int rbase = m0 + wm0 + mi * 16 + (lane >> 2);
#pragma unroll
        for (int nj = 0; nj < 4; nj++) {
            const int c = n0 + wn0 + nj * 8 + ((lane & 3) << 1);
#pragma unroll
            for (int half = 0; half < 2; half++) {
                const int rr = rbase + half * 8;
                if (rr < M) {
                    if (c < N) {
                        float v = acc[mi][nj][half * 2 + 0] + bias[c];
                        if (RELU) v = fmaxf(v, 0.f);
                        C[(size_t)rr * N + c] = v;
                    }
                    if (c + 1 < N) {
                        float v = acc[mi][nj][half * 2 + 1] + bias[c + 1];
                        if (RELU) v = fmaxf(v, 0.f);
                        C[(size_t)rr * N + c + 1] = v;
                    }
                }
            }
        }
    }
#undef GLOAD
#undef SSTORE
}

// ---------------------------------------------------------------------------
// Feature-map transpose: [C,H,W] -> [H*W, C]  (coalesced channel reads later)
// ---------------------------------------------------------------------------
__global__ void transpose_fm(const float* __restrict__ FM) {
    int idx = blockIdx.x * 256 + threadIdx.x;     // 2500*512 elements
    int pos = idx >> 9;
    int c   = idx & 511;
    g_fmt[idx] = FM[c * 2500 + pos];
}

// ---------------------------------------------------------------------------
// ROI max-pool. One block per box, 256 threads over channels.
// ---------------------------------------------------------------------------
__global__ void roi_pool(const float* __restrict__ P) {
    const int n = blockIdx.x;
    const int t = threadIdx.x;
    const float NEG_INF = __int_as_float(0xff800000);

    // boxes = proposals[:, [1,0,3,2]] -> (x1,y1,x2,y2)
    const float x1 = P[n * 4 + 1], y1 = P[n * 4 + 0];
    const float x2 = P[n * 4 + 3], y2 = P[n * 4 + 2];
    const float rsw = rintf(x1 * 0.0625f), rsh = rintf(y1 * 0.0625f);
    const float rew = rintf(x2 * 0.0625f), reh = rintf(y2 * 0.0625f);
    const float bw = fmaxf(rew - rsw + 1.f, 1.f) * (1.f / 7.f);
    const float bh = fmaxf(reh - rsh + 1.f, 1.f) * (1.f / 7.f);

    for (int bin = 0; bin < 49; bin++) {
        const int ph = bin / 7, pw = bin % 7;
        float hs = fminf(fmaxf(floorf((float)ph * bh) + rsh, 0.f), 50.f);
        float he = fminf(fmaxf(ceilf((float)(ph + 1) * bh) + rsh, 0.f), 50.f);
        float ws = fminf(fmaxf(floorf((float)pw * bw) + rsw, 0.f), 50.f);
        float we = fminf(fmaxf(ceilf((float)(pw + 1) * bw) + rsw, 0.f), 50.f);
        const bool empty = (he <= hs) || (we <= ws);
        const int hi = (int)hs, wi = (int)ws;
        const int hE = (int)he, wE = (int)we;

        for (int c = t; c < 512; c += 256) {
            float v;
            if (empty) {
                v = 0.f;
            } else {
                v = NEG_INF;
                for (int h = hi; h < hE; h++)
                    for (int w = wi; w < wE; w++)
                        v = fmaxf(v, g_fmt[(h * 50 + w) * 512 + c]);
            }
            g_rois2[(size_t)n * FLATF + c * 49 + bin] = v;
        }
    }
}

// ---------------------------------------------------------------------------
// Explicit im2col for the 4x4 VALID conv on 7x7 rois (clean rois only).
// row = n*16 + (oh*4+ow), k = ic*16 + kh*4 + kw
// ---------------------------------------------------------------------------
__global__ void im2col_k() {
    int idx = blockIdx.x * 256 + threadIdx.x;     // 8192*8192 elements
    int row = idx >> 13;
    int k   = idx & 8191;
    int n = row >> 4, pos = row & 15;
    int oh = pos >> 2, ow = pos & 3;
    int ic = k >> 4, rr = k & 15;
    int kh = rr >> 2, kw = rr & 3;
    g_im2col[(size_t)idx] =
        g_rois2[(size_t)n * FLATF + ic * 49 + (oh + kh) * 7 + (ow + kw)];
}

// ---------------------------------------------------------------------------
// Permute conv output [n][pos][oc] -> [n][oc*16+pos]  (so fc1's A is dense)
// ---------------------------------------------------------------------------
__global__ void permute_conv() {
    int idx = blockIdx.x * 256 + threadIdx.x;     // 512*8192
    int n = idx >> 13;
    int f = idx & 8191;
    int oc = f >> 4, pos = f & 15;
    g_xb[idx] = g_convt[(n * 16 + pos) * 512 + oc];
}

// ---------------------------------------------------------------------------
// Noise scale: ns[n] = mean_i sigmoid( h1[n,i,:] . w2 + b2 )
// ---------------------------------------------------------------------------
__global__ void ns_kernel(const float* __restrict__ W2, const float* __restrict__ B2) {
    const int n = blockIdx.x;
    const int t = threadIdx.x;
    const int w = t >> 5, lane = t & 31;
    __shared__ float sv[16];

    const float* row = &g_h1[(n * 16 + w) * 512];
    float s = 0.f;
    for (int j = lane; j < 512; j += 32) s += row[j] * W2[j];
#pragma unroll
    for (int o = 16; o; o >>= 1) s += __shfl_xor_sync(0xffffffffu, s, o);
    if (lane == 0) sv[w] = 1.f / (1.f + expf(-(s + B2[0])));
    __syncthreads();
    if (t == 0) {
        float m = 0.f;
        for (int i = 0; i < 16; i++) m += sv[i];
        g_ns[n] = m * (1.f / 16.f);
    }
}

// ---------------------------------------------------------------------------
// Box-Muller-style noise add: rows 512..1023 of g_rois2
// ---------------------------------------------------------------------------
__global__ void noise_kernel(const float* __restrict__ U) {
    int i = blockIdx.x * 256 + threadIdx.x;       // 512*25088
    int n = i / FLATF;
    g_rois2[(size_t)NBOX * FLATF + i] =
        g_rois2[i] + g_ns[n] * sqrtf(-2.f * logf(U[i]));
}

// ---------------------------------------------------------------------------
// Softmax(21) + copy reg deltas to output layout
// out: [classes 512x21][box_deltas 512x80][classes_n 512x21][box_deltas_n 512x80]
// ---------------------------------------------------------------------------
__global__ void finalize(float* __restrict__ out) {
    const int r = blockIdx.x;                     // 0..1023
    const int lane = threadIdx.x;                 // 32 threads
    const int n = (r < 512) ? r : r - 512;
    const int cbase = (r < 512) ? 0 : 51712;
    const int rbase = (r < 512) ? 10752 : 62464;
    const float NEG_INF = __int_as_float(0xff800000);

    float v = (lane < 21) ? g_cls[r * 21 + lane] : NEG_INF;
    float mx = v;
#pragma unroll
    for (int o = 16; o; o >>= 1) mx = fmaxf(mx, __shfl_xor_sync(0xffffffffu, mx, o));
    float e = (lane < 21) ? expf(v - mx) : 0.f;
    float s = e;
#pragma unroll
    for (int o = 16; o; o >>= 1) s += __shfl_xor_sync(0xffffffffu, s, o);
    if (lane < 21) out[cbase + n * 21 + lane] = e / s;

    for (int j = lane; j < 80; j += 32) out[rbase + n * 80 + j] = g_reg[r * 80 + j];
}

// ---------------------------------------------------------------------------
// Launch orchestration
// ---------------------------------------------------------------------------
extern "C" void kernel_launch(void* const* d_in, const int* in_sizes, int n_in,
                              void* d_out, int out_size)
{
    const float* FM = (const float*)d_in[0];
    const float* P  = (const float*)d_in[1];
    const float* U  = (const float*)d_in[2];
    const float* CW = (const float*)d_in[3];
    const float* CB = (const float*)d_in[4];
    const float* W1 = (const float*)d_in[5];
    const float* B1 = (const float*)d_in[6];
    const float* W2 = (const float*)d_in[7];
    const float* B2 = (const float*)d_in[8];
    const float* W6 = (const float*)d_in[9];
    const float* B6 = (const float*)d_in[10];
    const float* W7 = (const float*)d_in[11];
    const float* B7 = (const float*)d_in[12];
    const float* WC = (const float*)d_in[13];
    const float* BC = (const float*)d_in[14];
    const float* WR = (const float*)d_in[15];
    const float* BR = (const float*)d_in[16];
    float* OUT = (float*)d_out;

    float *p_rois2, *p_im2col, *p_convt, *p_xb, *p_h1, *p_y6, *p_y7, *p_cls, *p_reg;
    cudaGetSymbolAddress((void**)&p_rois2, g_rois2);
    cudaGetSymbolAddress((void**)&p_im2col, g_im2col);
    cudaGetSymbolAddress((void**)&p_convt, g_convt);
    cudaGetSymbolAddress((void**)&p_xb, g_xb);
    cudaGetSymbolAddress((void**)&p_h1, g_h1);
    cudaGetSymbolAddress((void**)&p_y6, g_y6);
    cudaGetSymbolAddress((void**)&p_y7, g_y7);
    cudaGetSymbolAddress((void**)&p_cls, g_cls);
    cudaGetSymbolAddress((void**)&p_reg, g_reg);

    // 1) transpose feature map for coalesced channel access
    transpose_fm<<<5000, 256>>>(FM);
    // 2) roi max-pool -> clean rois (rows 0..511 of g_rois2)
    roi_pool<<<NBOX, 256>>>(P);
    // 3) im2col for the noise-branch conv
    im2col_k<<<262144, 256>>>();
    // 4) conv as GEMM: [8192 x 8192] x [512 x 8192]^T, bias+relu
    gemm_tf32<true><<<dim3(4, 64), 256>>>(p_im2col, CW, CB, p_convt, M16, 512, CONVK);
    // 5) permute to [n][oc*16+pos]
    permute_conv<<<16384, 256>>>();
    // 6) fc1: [8192 x 512] x [512 x 512]^T, bias+relu
    gemm_tf32<true><<<dim3(4, 64), 256>>>(p_xb, W1, B1, p_h1, M16, 512, 512);
    // 7) noise scale reduction
    ns_kernel<<<NBOX, 512>>>(W2, B2);
    // 8) add noise -> rows 512..1023 of g_rois2
    noise_kernel<<<50176, 256>>>(U);
    // 9) FC6 on concat [1024 x 25088] (clean + noisy share one weight read)
    gemm_tf32<true><<<dim3(32, 8), 256>>>(p_rois2, W6, B6, p_y6, 2 * NBOX, FVS, FLATF);
    // 10) FC7
    gemm_tf32<true><<<dim3(32, 8), 256>>>(p_y6, W7, B7, p_y7, 2 * NBOX, FVS, FVS);
    // 11) heads
    gemm_tf32<false><<<dim3(1, 8), 256>>>(p_y7, WC, BC, p_cls, 2 * NBOX, 21, FVS);
    gemm_tf32<false><<<dim3(1, 8), 256>>>(p_y7, WR, BR, p_reg, 2 * NBOX, 80, FVS);
    // 12) softmax + output assembly
    finalize<<<2 * NBOX, 32>>>(OUT);
}

// round 4
// speedup vs baseline: 1.9760x; 1.9760x over previous
#include <cuda_runtime.h>
#include <cuda_fp16.h>
#include <cstdint>

// ---------------------------------------------------------------------------
// Problem constants
// ---------------------------------------------------------------------------
#define NBOX   512
#define FLATF  25088            // 512*7*7
#define CONVK  8192             // 512*4*4
#define M16    8192             // 512 * 16 conv output positions
#define FVS    4096
#define NHPAD  256              // heads padded: 21 cls + 80 reg -> 256

// ---------------------------------------------------------------------------
// Device scratch (fp16 everywhere the GEMMs touch)
// ---------------------------------------------------------------------------
__device__ __align__(16) __half g_fmth[50 * 50 * 512];
__device__ __align__(16) __half g_rois2h[2 * NBOX * FLATF];
__device__ __align__(16) __half g_im2colh[(size_t)M16 * CONVK];
__device__ __align__(16) __half g_cwh[512 * CONVK];
__device__ __align__(16) __half g_w1h[512 * 512];
__device__ __align__(16) __half g_w6h[(size_t)FVS * FLATF];
__device__ __align__(16) __half g_w7h[(size_t)FVS * FVS];
__device__ __align__(16) __half g_whh[NHPAD * FVS];
__device__ __align__(16) float  g_bhh[NHPAD];
__device__ __align__(16) __half g_convth[M16 * 512];
__device__ __align__(16) __half g_xbh[NBOX * CONVK];
__device__ __align__(16) __half g_h1h[M16 * 512];
__device__ float g_ns[NBOX];
__device__ __align__(16) __half g_y6h[2 * NBOX * FVS];
__device__ __align__(16) __half g_y7h[2 * NBOX * FVS];
__device__ __align__(16) float  g_head[2 * NBOX * NHPAD];

// ---------------------------------------------------------------------------
// PTX helpers (base-arch only: cp.async / ldmatrix / mma.sync)
// ---------------------------------------------------------------------------
__device__ __forceinline__ uint32_t smem_u32(const void* p) {
    uint32_t a;
    asm("{ .reg .u64 t; cvta.to.shared.u64 t, %1; cvt.u32.u64 %0, t; }" : "=r"(a) : "l"(p));
    return a;
}

#define CP_ASYNC16(sa, g) \
    asm volatile("cp.async.cg.shared.global [%0], [%1], 16;" :: "r"(sa), "l"(g))
#define CP_COMMIT() asm volatile("cp.async.commit_group;" ::: "memory")
#define CP_WAIT1()  asm volatile("cp.async.wait_group 1;" ::: "memory")

__device__ __forceinline__ void ldsm4(uint32_t r[4], uint32_t sa) {
    asm volatile("ldmatrix.sync.aligned.m8n8.x4.shared.b16 {%0,%1,%2,%3}, [%4];"
                 : "=r"(r[0]), "=r"(r[1]), "=r"(r[2]), "=r"(r[3]) : "r"(sa));
}

__device__ __forceinline__ void mma16816(float d[4], const uint32_t a[4],
                                         uint32_t b0, uint32_t b1) {
    asm volatile("mma.sync.aligned.m16n8k16.row.col.f32.f16.f16.f32 "
                 "{%0,%1,%2,%3}, {%4,%5,%6,%7}, {%8,%9}, {%0,%1,%2,%3};"
                 : "+f"(d[0]), "+f"(d[1]), "+f"(d[2]), "+f"(d[3])
                 : "r"(a[0]), "r"(a[1]), "r"(a[2]), "r"(a[3]), "r"(b0), "r"(b1));
}

// ---------------------------------------------------------------------------
// fp16 GEMM:  C[m][n] = act( sum_k A[m][k]*B[n][k] + bias[n] )
// BM=128, BN=256, BK=64, 512 threads (16 warps as 2x8, warp tile 64x32),
// 3-stage cp.async pipeline, padded smem rows (72 halves) -> conflict-free
// ldmatrix. Requires M%128==0, N%256==0, K%64==0 (all satisfied by padding).
// ---------------------------------------------------------------------------
#define RSTRIDE 144              // 72 halves * 2B
#define A_STG   18432            // 128 * 144
#define B_STG   36864            // 256 * 144
#define STG     (A_STG + B_STG)  // 55296
#define GSMEM   (3 * STG)        // 165888

template <bool RELU, bool HALF_OUT>
__global__ void __launch_bounds__(512, 1)
gemm_fp16(const __half* __restrict__ A, const __half* __restrict__ B,
          const float* __restrict__ bias, void* __restrict__ Cout,
          int M, int N, int K)
{
    extern __shared__ __align__(16) char smem[];
    const uint32_t sbase = smem_u32(smem);

    const int t    = threadIdx.x;
    const int lane = t & 31;
    const int wid  = t >> 5;
    const int m0   = blockIdx.y << 7;
    const int n0   = blockIdx.x << 8;
    const int wm   = (wid >> 3) << 6;          // 0 / 64
    const int wn   = (wid & 7) << 5;           // 0..224

    // --- loader precompute (6 chunks of 16B per thread per stage)
    // ids 0..1023 -> A (row=id>>3, c=id&7); 1024..3071 -> B
    int l_soff[6];
    const __half* l_gbase[6];
#pragma unroll
    for (int i = 0; i < 6; i++) {
        int id = t + i * 512;
        if (id < 1024) {
            int row = id >> 3, c = id & 7;
            l_soff[i]  = row * RSTRIDE + c * 16;
            l_gbase[i] = A + (size_t)(m0 + row) * K + c * 8;
        } else {
            int id2 = id - 1024;
            int row = id2 >> 3, c = id2 & 7;
            l_soff[i]  = A_STG + row * RSTRIDE + c * 16;
            l_gbase[i] = B + (size_t)(n0 + row) * K + c * 8;
        }
    }

#define ISSUE(slot, kt)                                                        \
    {                                                                          \
        const uint32_t sb = sbase + (slot) * STG;                              \
        const int koff = (kt) << 6;                                            \
        _Pragma("unroll")                                                      \
        for (int i = 0; i < 6; i++)                                            \
            CP_ASYNC16(sb + l_soff[i], l_gbase[i] + koff);                     \
        CP_COMMIT();                                                           \
    }

    float acc[4][4][4];
#pragma unroll
    for (int a = 0; a < 4; a++)
#pragma unroll
        for (int b = 0; b < 4; b++)
#pragma unroll
            for (int r = 0; r < 4; r++) acc[a][b][r] = 0.f;

    const int KT = K >> 6;

    ISSUE(0, 0);
    ISSUE(1, 1);
    CP_WAIT1();
    __syncthreads();

    // ldmatrix per-lane address components
    const int lrow = lane & 15;
    const int lkb  = (lane >> 4) << 4;        // 0 or 16 bytes (8 halves)

    int slot = 0;
    for (int kt = 0; kt < KT; kt++) {
        if (kt + 2 < KT) {
            int s2 = slot + 2; if (s2 >= 3) s2 -= 3;
            ISSUE(s2, kt + 2);
        } else {
            CP_COMMIT();
        }

        const uint32_t sA = sbase + slot * STG;
        const uint32_t sB = sA + A_STG;
#pragma unroll
        for (int ks = 0; ks < 4; ks++) {
            const int kb = ks * 32 + lkb;      // byte offset of k within stage
            uint32_t af[4][4];
#pragma unroll
            for (int mi = 0; mi < 4; mi++)
                ldsm4(af[mi], sA + (wm + mi * 16 + lrow) * RSTRIDE + kb);
            uint32_t bf[2][4];
#pragma unroll
            for (int bj = 0; bj < 2; bj++)
                ldsm4(bf[bj], sB + (wn + bj * 16 + lrow) * RSTRIDE + kb);
#pragma unroll
            for (int mi = 0; mi < 4; mi++)
#pragma unroll
                for (int nj = 0; nj < 4; nj++)
                    mma16816(acc[mi][nj], af[mi],
                             bf[nj >> 1][nj & 1], bf[nj >> 1][2 + (nj & 1)]);
        }

        CP_WAIT1();
        __syncthreads();
        if (++slot == 3) slot = 0;
    }

    // epilogue
    const int g = lane >> 2, cp2 = (lane & 3) << 1;
#pragma unroll
    for (int nj = 0; nj < 4; nj++) {
        const int col = n0 + wn + nj * 8 + cp2;
        const float b0 = bias[col], b1 = bias[col + 1];
#pragma unroll
        for (int mi = 0; mi < 4; mi++) {
            const int r0 = m0 + wm + mi * 16 + g;
#pragma unroll
            for (int h = 0; h < 2; h++) {
                float v0 = acc[mi][nj][h * 2 + 0] + b0;
                float v1 = acc[mi][nj][h * 2 + 1] + b1;
                if (RELU) { v0 = fmaxf(v0, 0.f); v1 = fmaxf(v1, 0.f); }
                const size_t off = (size_t)(r0 + h * 8) * N + col;
                if (HALF_OUT)
                    *(__half2*)((__half*)Cout + off) = __floats2half2_rn(v0, v1);
                else
                    *(float2*)((float*)Cout + off) = make_float2(v0, v1);
            }
        }
    }
#undef ISSUE
}

// ---------------------------------------------------------------------------
// Glue kernels
// ---------------------------------------------------------------------------
__global__ void f2h(const float* __restrict__ src, __half* __restrict__ dst, int n4) {
    int i = blockIdx.x * 256 + threadIdx.x;
    if (i < n4) {
        float4 v = ((const float4*)src)[i];
        __half2* d = (__half2*)dst + (size_t)i * 2;
        d[0] = __floats2half2_rn(v.x, v.y);
        d[1] = __floats2half2_rn(v.z, v.w);
    }
}

__global__ void transpose_fm(const float* __restrict__ FM) {
    int idx = blockIdx.x * 256 + threadIdx.x;      // 2500*512
    int pos = idx >> 9, c = idx & 511;
    g_fmth[idx] = __float2half(FM[c * 2500 + pos]);
}

__global__ void roi_pool(const float* __restrict__ P) {
    const int n = blockIdx.x;
    const int t = threadIdx.x;
    const float NEG_INF = __int_as_float(0xff800000);

    const float x1 = P[n * 4 + 1], y1 = P[n * 4 + 0];
    const float x2 = P[n * 4 + 3], y2 = P[n * 4 + 2];
    const float rsw = rintf(x1 * 0.0625f), rsh = rintf(y1 * 0.0625f);
    const float rew = rintf(x2 * 0.0625f), reh = rintf(y2 * 0.0625f);
    const float bw = fmaxf(rew - rsw + 1.f, 1.f) * (1.f / 7.f);
    const float bh = fmaxf(reh - rsh + 1.f, 1.f) * (1.f / 7.f);

    for (int bin = 0; bin < 49; bin++) {
        const int ph = bin / 7, pw = bin % 7;
        float hs = fminf(fmaxf(floorf((float)ph * bh) + rsh, 0.f), 50.f);
        float he = fminf(fmaxf(ceilf((float)(ph + 1) * bh) + rsh, 0.f), 50.f);
        float ws = fminf(fmaxf(floorf((float)pw * bw) + rsw, 0.f), 50.f);
        float we = fminf(fmaxf(ceilf((float)(pw + 1) * bw) + rsw, 0.f), 50.f);
        const bool empty = (he <= hs) || (we <= ws);
        const int hi = (int)hs, wi = (int)ws;
        const int hE = (int)he, wE = (int)we;

        for (int c = t; c < 512; c += 256) {
            float v;
            if (empty) {
                v = 0.f;
            } else {
                v = NEG_INF;
                for (int h = hi; h < hE; h++)
                    for (int w = wi; w < wE; w++)
                        v = fmaxf(v, __half2float(g_fmth[(h * 50 + w) * 512 + c]));
            }
            g_rois2h[(size_t)n * FLATF + c * 49 + bin] = __float2half(v);
        }
    }
}

__global__ void im2col_k() {
    int idx = blockIdx.x * 256 + threadIdx.x;      // 8192*8192
    int row = idx >> 13, k = idx & 8191;
    int n = row >> 4, pos = row & 15;
    int oh = pos >> 2, ow = pos & 3;
    int ic = k >> 4, rr = k & 15;
    int kh = rr >> 2, kw = rr & 3;
    g_im2colh[(size_t)idx] =
        g_rois2h[(size_t)n * FLATF + ic * 49 + (oh + kh) * 7 + (ow + kw)];
}

__global__ void permute_conv() {
    int idx = blockIdx.x * 256 + threadIdx.x;      // 512*8192
    int n = idx >> 13, f = idx & 8191;
    int oc = f >> 4, pos = f & 15;
    g_xbh[idx] = g_convth[(n * 16 + pos) * 512 + oc];
}

__global__ void ns_kernel(const float* __restrict__ W2, const float* __restrict__ B2) {
    const int n = blockIdx.x;
    const int t = threadIdx.x;
    const int w = t >> 5, lane = t & 31;
    __shared__ float sv[16];

    const __half* row = &g_h1h[(n * 16 + w) * 512];
    float s = 0.f;
    for (int j = lane; j < 512; j += 32) s += __half2float(row[j]) * W2[j];
#pragma unroll
    for (int o = 16; o; o >>= 1) s += __shfl_xor_sync(0xffffffffu, s, o);
    if (lane == 0) sv[w] = 1.f / (1.f + expf(-(s + B2[0])));
    __syncthreads();
    if (t == 0) {
        float m = 0.f;
        for (int i = 0; i < 16; i++) m += sv[i];
        g_ns[n] = m * (1.f / 16.f);
    }
}

// noise: out = rois + ns * sqrt(-2 ln u), all on the FMA pipe (no MUFU).
__global__ void noise_kernel(const float* __restrict__ U) {
    const int n = blockIdx.y;
    const int j = blockIdx.x * 256 + threadIdx.x;   // FLATF = 98*256
    const int i = n * FLATF + j;

    const float u = U[i];
    const uint32_t b = __float_as_uint(u);
    int e = (int)(b >> 23) - 127;
    float m = __uint_as_float((b & 0x7fffffu) | 0x3f800000u);
    if (m > 1.41421356f) { m *= 0.5f; e += 1; }
    const float x = m - 1.f;
    const float z = x * x;
    float p = 7.0376836292e-2f;
    p = p * x - 1.1514610310e-1f;
    p = p * x + 1.1676998740e-1f;
    p = p * x - 1.2420140846e-1f;
    p = p * x + 1.4249322787e-1f;
    p = p * x - 1.6668057665e-1f;
    p = p * x + 2.0000714765e-1f;
    p = p * x - 2.4999993993e-1f;
    p = p * x + 3.3333331174e-1f;
    const float lnm = x + (x * z * p - 0.5f * z);
    const float lnu = lnm + (float)e * 0.69314718056f;
    float tt = fmaxf(-2.f * lnu, 1e-12f);
    // sqrt via rsqrt magic + 3 Newton iterations (FMA pipe)
    float r = __uint_as_float(0x5f3759dfu - (__float_as_uint(tt) >> 1));
    r = r * (1.5f - 0.5f * tt * r * r);
    r = r * (1.5f - 0.5f * tt * r * r);
    r = r * (1.5f - 0.5f * tt * r * r);
    const float y = tt * r;

    g_rois2h[(size_t)NBOX * FLATF + i] =
        __float2half(__half2float(g_rois2h[i]) + g_ns[n] * y);
}

__global__ void concat_heads(const float* __restrict__ WC, const float* __restrict__ BC,
                             const float* __restrict__ WR, const float* __restrict__ BR) {
    int idx = blockIdx.x * 256 + threadIdx.x;      // 256*4096
    int row = idx >> 12, c = idx & 4095;
    float v = (row < 21) ? WC[row * 4096 + c]
            : (row < 101) ? WR[(row - 21) * 4096 + c] : 0.f;
    g_whh[idx] = __float2half(v);
    if (idx < NHPAD)
        g_bhh[idx] = (idx < 21) ? BC[idx] : (idx < 101) ? BR[idx - 21] : 0.f;
}

__global__ void finalize(float* __restrict__ out) {
    const int r = blockIdx.x;                      // 0..1023
    const int lane = threadIdx.x;                  // 32
    const int n = (r < 512) ? r : r - 512;
    const int cbase = (r < 512) ? 0 : 51712;
    const int rbase = (r < 512) ? 10752 : 62464;
    const float NEG_INF = __int_as_float(0xff800000);

    float v = (lane < 21) ? g_head[r * NHPAD + lane] : NEG_INF;
    float mx = v;
#pragma unroll
    for (int o = 16; o; o >>= 1) mx = fmaxf(mx, __shfl_xor_sync(0xffffffffu, mx, o));
    float e = (lane < 21) ? expf(v - mx) : 0.f;
    float s = e;
#pragma unroll
    for (int o = 16; o; o >>= 1) s += __shfl_xor_sync(0xffffffffu, s, o);
    if (lane < 21) out[cbase + n * 21 + lane] = e / s;

    for (int j = lane; j < 80; j += 32) out[rbase + n * 80 + j] = g_head[r * NHPAD + 21 + j];
}

// ---------------------------------------------------------------------------
// Launch orchestration
// ---------------------------------------------------------------------------
extern "C" void kernel_launch(void* const* d_in, const int* in_sizes, int n_in,
                              void* d_out, int out_size)
{
    const float* FM = (const float*)d_in[0];
    const float* P  = (const float*)d_in[1];
    const float* U  = (const float*)d_in[2];
    const float* CW = (const float*)d_in[3];
    const float* CB = (const float*)d_in[4];
    const float* W1 = (const float*)d_in[5];
    const float* B1 = (const float*)d_in[6];
    const float* W2 = (const float*)d_in[7];
    const float* B2 = (const float*)d_in[8];
    const float* W6 = (const float*)d_in[9];
    const float* B6 = (const float*)d_in[10];
    const float* W7 = (const float*)d_in[11];
    const float* B7 = (const float*)d_in[12];
    const float* WC = (const float*)d_in[13];
    const float* BC = (const float*)d_in[14];
    const float* WR = (const float*)d_in[15];
    const float* BR = (const float*)d_in[16];
    float* OUT = (float*)d_out;

    __half *p_cwh, *p_w1h, *p_w6h, *p_w7h, *p_whh;
    __half *p_rois2h, *p_im2colh, *p_convth, *p_xbh, *p_h1h, *p_y6h, *p_y7h;
    float *p_bhh, *p_head;
    cudaGetSymbolAddress((void**)&p_cwh, g_cwh);
    cudaGetSymbolAddress((void**)&p_w1h, g_w1h);
    cudaGetSymbolAddress((void**)&p_w6h, g_w6h);
    cudaGetSymbolAddress((void**)&p_w7h, g_w7h);
    cudaGetSymbolAddress((void**)&p_whh, g_whh);
    cudaGetSymbolAddress((void**)&p_bhh, g_bhh);
    cudaGetSymbolAddress((void**)&p_rois2h, g_rois2h);
    cudaGetSymbolAddress((void**)&p_im2colh, g_im2colh);
    cudaGetSymbolAddress((void**)&p_convth, g_convth);
    cudaGetSymbolAddress((void**)&p_xbh, g_xbh);
    cudaGetSymbolAddress((void**)&p_h1h, g_h1h);
    cudaGetSymbolAddress((void**)&p_y6h, g_y6h);
    cudaGetSymbolAddress((void**)&p_y7h, g_y7h);
    cudaGetSymbolAddress((void**)&p_head, g_head);

    cudaFuncSetAttribute(gemm_fp16<true, true>,
                         cudaFuncAttributeMaxDynamicSharedMemorySize, GSMEM);
    cudaFuncSetAttribute(gemm_fp16<false, false>,
                         cudaFuncAttributeMaxDynamicSharedMemorySize, GSMEM);

    // weight conversions (fp32 -> fp16)
    f2h<<<(512 * CONVK / 4 + 255) / 256, 256>>>(CW, p_cwh, 512 * CONVK / 4);
    f2h<<<(512 * 512 / 4 + 255) / 256, 256>>>(W1, p_w1h, 512 * 512 / 4);
    f2h<<<(int)(((size_t)FVS * FLATF / 4 + 255) / 256), 256>>>(W6, p_w6h, (int)((size_t)FVS * FLATF / 4));
    f2h<<<(FVS * FVS / 4 + 255) / 256, 256>>>(W7, p_w7h, FVS * FVS / 4);
    concat_heads<<<4096, 256>>>(WC, BC, WR, BR);

    transpose_fm<<<5000, 256>>>(FM);
    roi_pool<<<NBOX, 256>>>(P);
    im2col_k<<<262144, 256>>>();
    // conv as GEMM: [8192 x 8192] x [512 x 8192]^T
    gemm_fp16<true, true><<<dim3(2, 64), 512, GSMEM>>>(p_im2colh, p_cwh, CB, p_convth, M16, 512, CONVK);
    permute_conv<<<16384, 256>>>();
    // fc1: [8192 x 512] x [512 x 512]^T
    gemm_fp16<true, true><<<dim3(2, 64), 512, GSMEM>>>(p_xbh, p_w1h, B1, p_h1h, M16, 512, 512);
    ns_kernel<<<NBOX, 512>>>(W2, B2);
    noise_kernel<<<dim3(98, NBOX), 256>>>(U);
    // FC6 on concat clean+noisy: [1024 x 25088] x [4096 x 25088]^T
    gemm_fp16<true, true><<<dim3(16, 8), 512, GSMEM>>>(p_rois2h, p_w6h, B6, p_y6h, 2 * NBOX, FVS, FLATF);
    // FC7: [1024 x 4096] x [4096 x 4096]^T
    gemm_fp16<true, true><<<dim3(16, 8), 512, GSMEM>>>(p_y6h, p_w7h, B7, p_y7h, 2 * NBOX, FVS, FVS);
    // fused heads (padded to 256): [1024 x 4096] x [256 x 4096]^T
    gemm_fp16<false, false><<<dim3(1, 8), 512, GSMEM>>>(p_y7h, p_whh, p_bhh, p_head, 2 * NBOX, NHPAD, FVS);
    finalize<<<2 * NBOX, 32>>>(OUT);
}

// round 5
// speedup vs baseline: 2.0975x; 1.0615x over previous
#include <cuda_runtime.h>
#include <cuda_fp16.h>
#include <cstdint>

// ---------------------------------------------------------------------------
// Problem constants
// ---------------------------------------------------------------------------
#define NBOX   512
#define FLATF  25088            // 512*7*7
#define CONVK  8192             // 512*4*4
#define M16    8192             // 512 * 16 conv output positions
#define FVS    4096
#define NHPAD  256              // heads padded: 21 cls + 80 reg -> 256

// ---------------------------------------------------------------------------
// Device scratch
// ---------------------------------------------------------------------------
__device__ __align__(16) __half g_fmth[50 * 50 * 512];
__device__ __align__(16) __half g_rois2h[2 * NBOX * FLATF];
__device__ __align__(16) __half g_im2colh[(size_t)M16 * CONVK];
__device__ __align__(16) __half g_cwh[512 * CONVK];
__device__ __align__(16) __half g_w1h[512 * 512];
__device__ __align__(16) __half g_w6h[(size_t)FVS * FLATF];
__device__ __align__(16) __half g_w7h[(size_t)FVS * FVS];
__device__ __align__(16) __half g_whh[NHPAD * FVS];
__device__ __align__(16) float  g_bhh[NHPAD];
__device__ __align__(16) __half g_convth[M16 * 512];
__device__ __align__(16) __half g_xbh[NBOX * CONVK];
__device__ __align__(16) __half g_h1h[M16 * 512];
__device__ float g_ns[NBOX];
__device__ __align__(16) __half g_y6h[2 * NBOX * FVS];
__device__ __align__(16) __half g_y7h[2 * NBOX * FVS];
__device__ __align__(16) float  g_head[2 * NBOX * NHPAD];

// ---------------------------------------------------------------------------
// PTX helpers
// ---------------------------------------------------------------------------
__device__ __forceinline__ uint32_t smem_u32(const void* p) {
    uint32_t a;
    asm("{ .reg .u64 t; cvta.to.shared.u64 t, %1; cvt.u32.u64 %0, t; }" : "=r"(a) : "l"(p));
    return a;
}

#define CP_ASYNC16(sa, g) \
    asm volatile("cp.async.cg.shared.global [%0], [%1], 16;" :: "r"(sa), "l"(g))
#define CP_COMMIT() asm volatile("cp.async.commit_group;" ::: "memory")
#define CP_WAIT1()  asm volatile("cp.async.wait_group 1;" ::: "memory")

__device__ __forceinline__ void ldsm4(uint32_t r[4], uint32_t sa) {
    asm volatile("ldmatrix.sync.aligned.m8n8.x4.shared.b16 {%0,%1,%2,%3}, [%4];"
                 : "=r"(r[0]), "=r"(r[1]), "=r"(r[2]), "=r"(r[3]) : "r"(sa));
}

__device__ __forceinline__ void mma16816(float d[4], const uint32_t a[4],
                                         uint32_t b0, uint32_t b1) {
    asm volatile("mma.sync.aligned.m16n8k16.row.col.f32.f16.f16.f32 "
                 "{%0,%1,%2,%3}, {%4,%5,%6,%7}, {%8,%9}, {%0,%1,%2,%3};"
                 : "+f"(d[0]), "+f"(d[1]), "+f"(d[2]), "+f"(d[3])
                 : "r"(a[0]), "r"(a[1]), "r"(a[2]), "r"(a[3]), "r"(b0), "r"(b1));
}

// ---------------------------------------------------------------------------
// fp16 GEMM:  C[m][n] = act( sum_k A[m][k]*B[n][k] + bias[n] )
// BM=128, BN=128, BK=64, 256 threads (8 warps as 2x4, warp tile 64x32),
// 3-stage cp.async pipeline, 110KB smem -> 2 CTAs/SM.
// Requires M%128==0, N%128==0, K%64==0.
// ---------------------------------------------------------------------------
#define RSTRIDE 144              // 72 halves * 2B (pad -> conflict-free ldsm)
#define A_STG   18432            // 128 * 144
#define STG     36864            // A + B
#define GSMEM   (3 * STG)        // 110592

template <bool RELU, bool HALF_OUT>
__global__ void __launch_bounds__(256, 2)
gemm_fp16(const __half* __restrict__ A, const __half* __restrict__ B,
          const float* __restrict__ bias, void* __restrict__ Cout,
          int M, int N, int K)
{
    extern __shared__ __align__(16) char smem[];
    const uint32_t sbase = smem_u32(smem);

    const int t    = threadIdx.x;
    const int lane = t & 31;
    const int wid  = t >> 5;
    const int m0   = blockIdx.y << 7;
    const int n0   = blockIdx.x << 7;
    const int wm   = (wid >> 2) << 6;          // 0 / 64
    const int wn   = (wid & 3) << 5;           // 0,32,64,96

    // loader: thread t covers A rows (t>>3)+32i and B rows (t>>3)+32i, col chunk t&7
    const int lrow0 = t >> 3;                  // 0..31
    const int lc    = t & 7;                   // 16B chunk
    const __half* gA = A + (size_t)(m0 + lrow0) * K + lc * 8;
    const __half* gB = B + (size_t)(n0 + lrow0) * K + lc * 8;
    const size_t  rstep = (size_t)32 * K;      // 32 rows down
    const uint32_t sAo = lrow0 * RSTRIDE + lc * 16;
    const uint32_t sBo = A_STG + sAo;

#define ISSUE(slot, kt)                                                        \
    {                                                                          \
        const uint32_t sb = sbase + (slot) * STG;                              \
        const int koff = (kt) << 6;                                            \
        _Pragma("unroll")                                                      \
        for (int i = 0; i < 4; i++)                                            \
            CP_ASYNC16(sb + sAo + i * (32 * RSTRIDE), gA + koff + i * rstep);  \
        _Pragma("unroll")                                                      \
        for (int i = 0; i < 4; i++)                                            \
            CP_ASYNC16(sb + sBo + i * (32 * RSTRIDE), gB + koff + i * rstep);  \
        CP_COMMIT();                                                           \
    }

    float acc[4][4][4];
#pragma unroll
    for (int a = 0; a < 4; a++)
#pragma unroll
        for (int b = 0; b < 4; b++)
#pragma unroll
            for (int r = 0; r < 4; r++) acc[a][b][r] = 0.f;

    const int KT = K >> 6;

    ISSUE(0, 0);
    ISSUE(1, 1);
    CP_WAIT1();
    __syncthreads();

    const int lrow = lane & 15;
    const int lkb  = (lane >> 4) << 4;         // 0 or 16 bytes

    int slot = 0;
    for (int kt = 0; kt < KT; kt++) {
        if (kt + 2 < KT) {
            int s2 = slot + 2; if (s2 >= 3) s2 -= 3;
            ISSUE(s2, kt + 2);
        } else {
            CP_COMMIT();
        }

        const uint32_t sA = sbase + slot * STG;
        const uint32_t sB = sA + A_STG;
#pragma unroll
        for (int ks = 0; ks < 4; ks++) {
            const int kb = ks * 32 + lkb;
            uint32_t af[4][4];
#pragma unroll
            for (int mi = 0; mi < 4; mi++)
                ldsm4(af[mi], sA + (wm + mi * 16 + lrow) * RSTRIDE + kb);
            uint32_t bf[2][4];
#pragma unroll
            for (int bj = 0; bj < 2; bj++)
                ldsm4(bf[bj], sB + (wn + bj * 16 + lrow) * RSTRIDE + kb);
#pragma unroll
            for (int mi = 0; mi < 4; mi++)
#pragma unroll
                for (int nj = 0; nj < 4; nj++)
                    mma16816(acc[mi][nj], af[mi],
                             bf[nj >> 1][nj & 1], bf[nj >> 1][2 + (nj & 1)]);
        }

        CP_WAIT1();
        __syncthreads();
        if (++slot == 3) slot = 0;
    }

    // epilogue
    const int g = lane >> 2, cp2 = (lane & 3) << 1;
#pragma unroll
    for (int nj = 0; nj < 4; nj++) {
        const int col = n0 + wn + nj * 8 + cp2;
        const float b0 = bias[col], b1 = bias[col + 1];
#pragma unroll
        for (int mi = 0; mi < 4; mi++) {
            const int r0 = m0 + wm + mi * 16 + g;
#pragma unroll
            for (int h = 0; h < 2; h++) {
                float v0 = acc[mi][nj][h * 2 + 0] + b0;
                float v1 = acc[mi][nj][h * 2 + 1] + b1;
                if (RELU) { v0 = fmaxf(v0, 0.f); v1 = fmaxf(v1, 0.f); }
                const size_t off = (size_t)(r0 + h * 8) * N + col;
                if (HALF_OUT)
                    *(__half2*)((__half*)Cout + off) = __floats2half2_rn(v0, v1);
                else
                    *(float2*)((float*)Cout + off) = make_float2(v0, v1);
            }
        }
    }
#undef ISSUE
}

// ---------------------------------------------------------------------------
// Glue kernels
// ---------------------------------------------------------------------------
__global__ void f2h(const float* __restrict__ src, __half* __restrict__ dst, int n4) {
    int i = blockIdx.x * 256 + threadIdx.x;
    if (i < n4) {
        float4 v = ((const float4*)src)[i];
        __half2* d = (__half2*)dst + (size_t)i * 2;
        d[0] = __floats2half2_rn(v.x, v.y);
        d[1] = __floats2half2_rn(v.z, v.w);
    }
}

__global__ void transpose_fm(const float* __restrict__ FM) {
    int idx = blockIdx.x * 256 + threadIdx.x;      // 2500*512
    int pos = idx >> 9, c = idx & 511;
    g_fmth[idx] = __float2half(FM[c * 2500 + pos]);
}

__global__ void roi_pool(const float* __restrict__ P) {
    const int n = blockIdx.x;
    const int t = threadIdx.x;
    const float NEG_INF = __int_as_float(0xff800000);

    const float x1 = P[n * 4 + 1], y1 = P[n * 4 + 0];
    const float x2 = P[n * 4 + 3], y2 = P[n * 4 + 2];
    const float rsw = rintf(x1 * 0.0625f), rsh = rintf(y1 * 0.0625f);
    const float rew = rintf(x2 * 0.0625f), reh = rintf(y2 * 0.0625f);
    const float bw = fmaxf(rew - rsw + 1.f, 1.f) * (1.f / 7.f);
    const float bh = fmaxf(reh - rsh + 1.f, 1.f) * (1.f / 7.f);

    for (int bin = 0; bin < 49; bin++) {
        const int ph = bin / 7, pw = bin % 7;
        float hs = fminf(fmaxf(floorf((float)ph * bh) + rsh, 0.f), 50.f);
        float he = fminf(fmaxf(ceilf((float)(ph + 1) * bh) + rsh, 0.f), 50.f);
        float ws = fminf(fmaxf(floorf((float)pw * bw) + rsw, 0.f), 50.f);
        float we = fminf(fmaxf(ceilf((float)(pw + 1) * bw) + rsw, 0.f), 50.f);
        const bool empty = (he <= hs) || (we <= ws);
        const int hi = (int)hs, wi = (int)ws;
        const int hE = (int)he, wE = (int)we;

        for (int c = t; c < 512; c += 256) {
            float v;
            if (empty) {
                v = 0.f;
            } else {
                v = NEG_INF;
                for (int h = hi; h < hE; h++)
                    for (int w = wi; w < wE; w++)
                        v = fmaxf(v, __half2float(g_fmth[(h * 50 + w) * 512 + c]));
            }
            g_rois2h[(size_t)n * FLATF + c * 49 + bin] = __float2half(v);
        }
    }
}

// im2col, 8 consecutive k per thread (one 16B store)
__global__ void im2col_k() {
    int id = blockIdx.x * 256 + threadIdx.x;       // 8.4M threads
    int row = id >> 10;                            // 8192 rows
    int chunk = id & 1023;                         // 1024 chunks of 8 k
    int n = row >> 4, pos = row & 15;
    int oh = pos >> 2, ow = pos & 3;
    int k0 = chunk << 3;
    int ic = k0 >> 4;
    int kh0 = (k0 & 15) >> 2;                      // 0 or 2

    const __half* src = &g_rois2h[(size_t)n * FLATF + ic * 49];
    __half v[8];
#pragma unroll
    for (int kh = 0; kh < 2; kh++) {
        const __half* r = src + (oh + kh0 + kh) * 7 + ow;
#pragma unroll
        for (int kw = 0; kw < 4; kw++) v[kh * 4 + kw] = r[kw];
    }
    *(uint4*)&g_im2colh[(size_t)id << 3] = *(uint4*)v;
}

__global__ void permute_conv() {
    int idx = blockIdx.x * 256 + threadIdx.x;      // 512*8192
    int n = idx >> 13, f = idx & 8191;
    int oc = f >> 4, pos = f & 15;
    g_xbh[idx] = g_convth[(n * 16 + pos) * 512 + oc];
}

__global__ void ns_kernel(const float* __restrict__ W2, const float* __restrict__ B2) {
    const int n = blockIdx.x;
    const int t = threadIdx.x;
    const int w = t >> 5, lane = t & 31;
    __shared__ float sv[16];

    const __half* row = &g_h1h[(n * 16 + w) * 512];
    float s = 0.f;
    for (int j = lane; j < 512; j += 32) s += __half2float(row[j]) * W2[j];
#pragma unroll
    for (int o = 16; o; o >>= 1) s += __shfl_xor_sync(0xffffffffu, s, o);
    if (lane == 0) sv[w] = 1.f / (1.f + expf(-(s + B2[0])));
    __syncthreads();
    if (t == 0) {
        float m = 0.f;
        for (int i = 0; i < 16; i++) m += sv[i];
        g_ns[n] = m * (1.f / 16.f);
    }
}

__device__ __forceinline__ float fast_sqrt_n2ln(float u) {
    const uint32_t b = __float_as_uint(u);
    int e = (int)(b >> 23) - 127;
    float m = __uint_as_float((b & 0x7fffffu) | 0x3f800000u);
    if (m > 1.41421356f) { m *= 0.5f; e += 1; }
    const float x = m - 1.f;
    const float z = x * x;
    float p = 7.0376836292e-2f;
    p = p * x - 1.1514610310e-1f;
    p = p * x + 1.1676998740e-1f;
    p = p * x - 1.2420140846e-1f;
    p = p * x + 1.4249322787e-1f;
    p = p * x - 1.6668057665e-1f;
    p = p * x + 2.0000714765e-1f;
    p = p * x - 2.4999993993e-1f;
    p = p * x + 3.3333331174e-1f;
    const float lnm = x + (x * z * p - 0.5f * z);
    const float lnu = lnm + (float)e * 0.69314718056f;
    float tt = fmaxf(-2.f * lnu, 1e-12f);
    float r = __uint_as_float(0x5f3759dfu - (__float_as_uint(tt) >> 1));
    r = r * (1.5f - 0.5f * tt * r * r);
    r = r * (1.5f - 0.5f * tt * r * r);
    r = r * (1.5f - 0.5f * tt * r * r);
    return tt * r;
}

// noise: out = rois + ns * sqrt(-2 ln u), x4 vectorized
__global__ void noise_kernel(const float* __restrict__ U) {
    const int n = blockIdx.y;
    const int j4 = blockIdx.x * 256 + threadIdx.x;   // FLATF/4 = 6272
    if (j4 >= FLATF / 4) return;
    const int i = n * FLATF + j4 * 4;

    float4 u = *(const float4*)(U + i);
    const float nsv = g_ns[n];
    float y0 = nsv * fast_sqrt_n2ln(u.x);
    float y1 = nsv * fast_sqrt_n2ln(u.y);
    float y2 = nsv * fast_sqrt_n2ln(u.z);
    float y3 = nsv * fast_sqrt_n2ln(u.w);

    const __half2* rp = (const __half2*)&g_rois2h[i];
    float2 r01 = __half22float2(rp[0]);
    float2 r23 = __half22float2(rp[1]);
    __half2 o01 = __floats2half2_rn(r01.x + y0, r01.y + y1);
    __half2 o23 = __floats2half2_rn(r23.x + y2, r23.y + y3);
    __half2* op = (__half2*)&g_rois2h[(size_t)NBOX * FLATF + i];
    op[0] = o01; op[1] = o23;
}

__global__ void concat_heads(const float* __restrict__ WC, const float* __restrict__ BC,
                             const float* __restrict__ WR, const float* __restrict__ BR) {
    int idx = blockIdx.x * 256 + threadIdx.x;      // 256*4096
    int row = idx >> 12, c = idx & 4095;
    float v = (row < 21) ? WC[row * 4096 + c]
            : (row < 101) ? WR[(row - 21) * 4096 + c] : 0.f;
    g_whh[idx] = __float2half(v);
    if (idx < NHPAD)
        g_bhh[idx] = (idx < 21) ? BC[idx] : (idx < 101) ? BR[idx - 21] : 0.f;
}

__global__ void finalize(float* __restrict__ out) {
    const int r = blockIdx.x;                      // 0..1023
    const int lane = threadIdx.x;                  // 32
    const int n = (r < 512) ? r : r - 512;
    const int cbase = (r < 512) ? 0 : 51712;
    const int rbase = (r < 512) ? 10752 : 62464;
    const float NEG_INF = __int_as_float(0xff800000);

    float v = (lane < 21) ? g_head[r * NHPAD + lane] : NEG_INF;
    float mx = v;
#pragma unroll
    for (int o = 16; o; o >>= 1) mx = fmaxf(mx, __shfl_xor_sync(0xffffffffu, mx, o));
    float e = (lane < 21) ? expf(v - mx) : 0.f;
    float s = e;
#pragma unroll
    for (int o = 16; o; o >>= 1) s += __shfl_xor_sync(0xffffffffu, s, o);
    if (lane < 21) out[cbase + n * 21 + lane] = e / s;

    for (int j = lane; j < 80; j += 32) out[rbase + n * 80 + j] = g_head[r * NHPAD + 21 + j];
}

// ---------------------------------------------------------------------------
// Launch orchestration
// ---------------------------------------------------------------------------
extern "C" void kernel_launch(void* const* d_in, const int* in_sizes, int n_in,
                              void* d_out, int out_size)
{
    const float* FM = (const float*)d_in[0];
    const float* P  = (const float*)d_in[1];
    const float* U  = (const float*)d_in[2];
    const float* CW = (const float*)d_in[3];
    const float* CB = (const float*)d_in[4];
    const float* W1 = (const float*)d_in[5];
    const float* B1 = (const float*)d_in[6];
    const float* W2 = (const float*)d_in[7];
    const float* B2 = (const float*)d_in[8];
    const float* W6 = (const float*)d_in[9];
    const float* B6 = (const float*)d_in[10];
    const float* W7 = (const float*)d_in[11];
    const float* B7 = (const float*)d_in[12];
    const float* WC = (const float*)d_in[13];
    const float* BC = (const float*)d_in[14];
    const float* WR = (const float*)d_in[15];
    const float* BR = (const float*)d_in[16];
    float* OUT = (float*)d_out;

    __half *p_cwh, *p_w1h, *p_w6h, *p_w7h, *p_whh;
    __half *p_rois2h, *p_im2colh, *p_convth, *p_xbh, *p_h1h, *p_y6h, *p_y7h;
    float *p_bhh, *p_head;
    cudaGetSymbolAddress((void**)&p_cwh, g_cwh);
    cudaGetSymbolAddress((void**)&p_w1h, g_w1h);
    cudaGetSymbolAddress((void**)&p_w6h, g_w6h);
    cudaGetSymbolAddress((void**)&p_w7h, g_w7h);
    cudaGetSymbolAddress((void**)&p_whh, g_whh);
    cudaGetSymbolAddress((void**)&p_bhh, g_bhh);
    cudaGetSymbolAddress((void**)&p_rois2h, g_rois2h);
    cudaGetSymbolAddress((void**)&p_im2colh, g_im2colh);
    cudaGetSymbolAddress((void**)&p_convth, g_convth);
    cudaGetSymbolAddress((void**)&p_xbh, g_xbh);
    cudaGetSymbolAddress((void**)&p_h1h, g_h1h);
    cudaGetSymbolAddress((void**)&p_y6h, g_y6h);
    cudaGetSymbolAddress((void**)&p_y7h, g_y7h);
    cudaGetSymbolAddress((void**)&p_head, g_head);

    cudaFuncSetAttribute(gemm_fp16<true, true>,
                         cudaFuncAttributeMaxDynamicSharedMemorySize, GSMEM);
    cudaFuncSetAttribute(gemm_fp16<false, false>,
                         cudaFuncAttributeMaxDynamicSharedMemorySize, GSMEM);

    // order chosen so the conv GEMM lands in ncu's -s 5 -c 1 window
    transpose_fm<<<5000, 256>>>(FM);                                            // 1
    roi_pool<<<NBOX, 256>>>(P);                                                 // 2
    f2h<<<(512 * CONVK / 4 + 255) / 256, 256>>>(CW, p_cwh, 512 * CONVK / 4);    // 3
    im2col_k<<<32768, 256>>>();                                                 // 4
    f2h<<<(512 * 512 / 4 + 255) / 256, 256>>>(W1, p_w1h, 512 * 512 / 4);        // 5
    // conv as GEMM: [8192 x 8192] x [512 x 8192]^T                             // 6
    gemm_fp16<true, true><<<dim3(4, 64), 256, GSMEM>>>(p_im2colh, p_cwh, CB, p_convth, M16, 512, CONVK);
    permute_conv<<<16384, 256>>>();
    // fc1: [8192 x 512] x [512 x 512]^T
    gemm_fp16<true, true><<<dim3(4, 64), 256, GSMEM>>>(p_xbh, p_w1h, B1, p_h1h, M16, 512, 512);
    ns_kernel<<<NBOX, 512>>>(W2, B2);
    noise_kernel<<<dim3(25, NBOX), 256>>>(U);
    f2h<<<(int)(((size_t)FVS * FLATF / 4 + 255) / 256), 256>>>(W6, p_w6h, (int)((size_t)FVS * FLATF / 4));
    f2h<<<(FVS * FVS / 4 + 255) / 256, 256>>>(W7, p_w7h, FVS * FVS / 4);
    concat_heads<<<4096, 256>>>(WC, BC, WR, BR);
    // FC6 on concat clean+noisy: [1024 x 25088] x [4096 x 25088]^T
    gemm_fp16<true, true><<<dim3(32, 8), 256, GSMEM>>>(p_rois2h, p_w6h, B6, p_y6h, 2 * NBOX, FVS, FLATF);
    // FC7: [1024 x 4096] x [4096 x 4096]^T
    gemm_fp16<true, true><<<dim3(32, 8), 256, GSMEM>>>(p_y6h, p_w7h, B7, p_y7h, 2 * NBOX, FVS, FVS);
    // fused heads (padded to 256): [1024 x 4096] x [256 x 4096]^T
    gemm_fp16<false, false><<<dim3(2, 8), 256, GSMEM>>>(p_y7h, p_whh, p_bhh, p_head, 2 * NBOX, NHPAD, FVS);
    finalize<<<2 * NBOX, 32>>>(OUT);
}